// round 1
// baseline (speedup 1.0000x reference)
#include <cuda_runtime.h>
#include <cstdint>

// Problem constants (from reference): B=256, T=512, C=256, L=64, S=129
#define Bb 256
#define Tt 512
#define Cc 256
#define Ll 64
#define GQW 65   // per-(b,t) compact log-prob row: [blank, label_0 .. label_63]

static __device__ float g_gq[(size_t)Bb * Tt * GQW];   // 34 MB scratch (log2-domain log-probs)
static __device__ float g_loss[Bb];

__device__ __forceinline__ float ex2f_(float x) {
    float y; asm("ex2.approx.ftz.f32 %0, %1;" : "=f"(y) : "f"(x)); return y;
}
__device__ __forceinline__ float lg2f_(float x) {
    float y; asm("lg2.approx.f32 %0, %1;" : "=f"(y) : "f"(x)); return y;
}

#define NEGF   (-1e30f)
#define LOG2E  1.4426950408889634f
#define LN2    0.6931471805599453f

// log2-domain logaddexp: log2(2^a + 2^b)
__device__ __forceinline__ float lse2(float a, float b) {
    float m = fmaxf(a, b);
    float d = fminf(a, b) - m;           // <= 0; (-1e30 - -1e30) = 0 -> fine
    return m + lg2f_(1.0f + ex2f_(d));
}
// log2-domain 3-way
__device__ __forceinline__ float lse3(float a, float b, float c) {
    float m = fmaxf(fmaxf(a, b), c);
    return m + lg2f_(ex2f_(a - m) + ex2f_(b - m) + ex2f_(c - m));
}

// ---------------------------------------------------------------------------
// Kernel 1: per-(b,t) log_softmax lse + gather of 65 needed log-probs
// (stored in log2 domain). Warp per row, 8 warps per block.
// ---------------------------------------------------------------------------
__global__ void __launch_bounds__(256) k_logits(const float* __restrict__ logits,
                                                const int* __restrict__ targets) {
    __shared__ float rows[8][Cc];
    int wid  = threadIdx.x >> 5;
    int lane = threadIdx.x & 31;
    int w = blockIdx.x * 8 + wid;        // w in [0, B*T)
    int b = w >> 9;                      // T = 512
    const float* __restrict__ row = logits + (size_t)w * Cc;

    float v[8];
    float m = -3.4e38f;
#pragma unroll
    for (int i = 0; i < 8; i++) {
        v[i] = row[lane + 32 * i];
        rows[wid][lane + 32 * i] = v[i];
        m = fmaxf(m, v[i]);
    }
#pragma unroll
    for (int off = 16; off; off >>= 1)
        m = fmaxf(m, __shfl_xor_sync(0xffffffffu, m, off));
    float s = 0.0f;
#pragma unroll
    for (int i = 0; i < 8; i++)
        s += ex2f_((v[i] - m) * LOG2E);
#pragma unroll
    for (int off = 16; off; off >>= 1)
        s += __shfl_xor_sync(0xffffffffu, s, off);
    float lse = m + lg2f_(s) * LN2;      // natural-log logsumexp of the row

    __syncwarp();
    float* __restrict__ out = g_gq + (size_t)w * GQW;
    const int* __restrict__ tg = targets + b * Ll;
#pragma unroll
    for (int j = lane; j < GQW; j += 32) {
        int c = (j == 0) ? 0 : tg[j - 1];        // blank=0, else target label
        out[j] = (rows[wid][c] - lse) * LOG2E;   // log2 domain
    }
}

// ---------------------------------------------------------------------------
// Kernel 2: CTC forward DP, one warp per batch row, 4 states per lane
// (s = 4*lane + k), state 128 as an extra scalar on lane 31.
// 2 warps per block so each warp gets its own SMSP on its own SM.
// ---------------------------------------------------------------------------
__global__ void __launch_bounds__(64) k_dp(const int* __restrict__ targets,
                                           const int* __restrict__ in_len,
                                           const int* __restrict__ tg_len) {
    __shared__ float As[2][132];
    int wid  = threadIdx.x >> 5;
    int lane = threadIdx.x & 31;
    int b = blockIdx.x * 2 + wid;

    const int* __restrict__ tg = targets + b * Ll;
    // gq row indices for the two odd (label) states of this lane
    int i1 = 2 * lane + 1;               // state s=4*lane+1 -> label tg[2*lane]
    int i3 = 2 * lane + 2;               // state s=4*lane+3 -> label tg[2*lane+1]
    int t1 = tg[2 * lane];
    int t3 = tg[2 * lane + 1];
    bool skip1 = (lane > 0) && (t1 != tg[2 * lane - 1]);
    bool skip3 = (t3 != t1);

    int Tin = in_len[b];
    int tl  = tg_len[b];
    const float* __restrict__ row = g_gq + (size_t)b * Tt * GQW;

    float a0 = NEGF, a1 = NEGF, a2 = NEGF, a3 = NEGF, aT = NEGF;
    if (lane == 0) { a0 = row[0]; a1 = row[1]; }   // alpha at t=0

    // prefetch t=1
    const float* rp = row + GQW;
    float bl_n = __ldg(rp);
    float l1_n = __ldg(rp + i1);
    float l3_n = __ldg(rp + i3);

    for (int t = 1; t < Tin; t++) {
        float bl = bl_n, lp1 = l1_n, lp3 = l3_n;
        if (t + 1 < Tin) {
            const float* r2 = row + (size_t)(t + 1) * GQW;
            bl_n = __ldg(r2);
            l1_n = __ldg(r2 + i1);
            l3_n = __ldg(r2 + i3);
        }
        float p3 = __shfl_up_sync(0xffffffffu, a3, 1);  // prev lane's s=4l-1
        if (lane == 0) p3 = NEGF;

        // s=4l   (blank): from s, s-1
        float n0 = lse2(a0, p3) + bl;
        // s=4l+1 (label): from s, s-1, (s-2 if skip)
        float n1 = lse3(a1, a0, skip1 ? p3 : NEGF) + lp1;
        // s=4l+2 (blank): from s, s-1
        float n2 = lse2(a2, a1) + bl;
        // s=4l+3 (label): from s, s-1, (s-2 if skip)
        float n3 = lse3(a3, a2, skip3 ? a1 : NEGF) + lp3;
        // s=128  (blank, valid on lane 31): from s, s-1 (=a3 old)
        float nT = lse2(aT, a3) + bl;

        a0 = fmaxf(n0, NEGF);
        a1 = fmaxf(n1, NEGF);
        a2 = fmaxf(n2, NEGF);
        a3 = fmaxf(n3, NEGF);
        aT = fmaxf(nT, NEGF);
    }

    As[wid][lane * 4 + 0] = a0;
    As[wid][lane * 4 + 1] = a1;
    As[wid][lane * 4 + 2] = a2;
    As[wid][lane * 4 + 3] = a3;
    if (lane == 31) As[wid][128] = aT;
    __syncwarp();

    if (lane == 0) {
        float fa = As[wid][2 * tl];          // alpha[2*tl]
        float fb = As[wid][2 * tl - 1];      // alpha[2*tl-1]
        float loss = -LN2 * lse2(fa, fb);    // back to natural log
        if (!(loss <= 1e20f)) loss = 0.0f;   // zero_infinity
        g_loss[b] = loss / (float)tl;
    }
}

// ---------------------------------------------------------------------------
// Kernel 3: deterministic mean over batch -> scalar output
// ---------------------------------------------------------------------------
__global__ void __launch_bounds__(256) k_red(float* __restrict__ out) {
    __shared__ float sh[256];
    int tid = threadIdx.x;
    sh[tid] = g_loss[tid];
    __syncthreads();
#pragma unroll
    for (int off = 128; off; off >>= 1) {
        if (tid < off) sh[tid] += sh[tid + off];
        __syncthreads();
    }
    if (tid == 0) out[0] = sh[0] * (1.0f / 256.0f);
}

extern "C" void kernel_launch(void* const* d_in, const int* in_sizes, int n_in,
                              void* d_out, int out_size) {
    const float* logits  = (const float*)d_in[0];   // [B,T,C] f32
    const int*   targets = (const int*)d_in[1];     // [B,L] i32
    const int*   in_len  = (const int*)d_in[2];     // [B] i32
    const int*   tg_len  = (const int*)d_in[3];     // [B] i32

    k_logits<<<(Bb * Tt) / 8, 256>>>(logits, targets);
    k_dp<<<Bb / 2, 64>>>(targets, in_len, tg_len);
    k_red<<<1, 256>>>((float*)d_out);
}